// round 14
// baseline (speedup 1.0000x reference)
#include <cuda_runtime.h>
#include <cuda_bf16.h>
#include <math.h>
#include <stdint.h>

// Problem constants: N=64, T=512, D=512, H=512, fp32
#define NB   64
#define TT   512
#define DD   512
#define HH   512

// ---------------------------------------------------------------------------
// f32x2 packed-math helpers
// ---------------------------------------------------------------------------
__device__ __forceinline__ void ffma2(unsigned long long& acc,
                                      unsigned long long a,
                                      unsigned long long b) {
    asm("fma.rn.f32x2 %0, %1, %2, %0;" : "+l"(acc) : "l"(a), "l"(b));
}
__device__ __forceinline__ unsigned long long add2(unsigned long long a,
                                                   unsigned long long b) {
    unsigned long long r;
    asm("add.rn.f32x2 %0, %1, %2;" : "=l"(r) : "l"(a), "l"(b));
    return r;
}
__device__ __forceinline__ unsigned long long pack_dup(float v) {
    unsigned long long r;
    unsigned u = __float_as_uint(v);
    asm("mov.b64 %0, {%1, %1};" : "=l"(r) : "r"(u));
    return r;
}
__device__ __forceinline__ unsigned long long pack2(float lo, float hi) {
    unsigned long long r;
    asm("mov.b64 %0, {%1, %2};" : "=l"(r) : "f"(lo), "f"(hi));
    return r;
}

// mbarrier helpers -----------------------------------------------------------
#define MBAR_INIT(addr, cnt) \
    asm volatile("mbarrier.init.shared.b64 [%0], %1;" :: "r"(addr), "r"(cnt) : "memory")
#define MBAR_EXPECT_TX(addr, bytes) \
    asm volatile("mbarrier.arrive.expect_tx.shared.b64 _, [%0], %1;" \
                 :: "r"(addr), "r"(bytes) : "memory")

__device__ __forceinline__ void mbar_wait_parity(uint32_t mbar, uint32_t parity) {
    asm volatile(
        "{\n\t"
        ".reg .pred P;\n\t"
        "WL_%=:\n\t"
        "mbarrier.try_wait.parity.acquire.cluster.shared::cta.b64 P, [%0], %1, 0x989680;\n\t"
        "@P bra WD_%=;\n\t"
        "bra WL_%=;\n\t"
        "WD_%=:\n\t"
        "}" :: "r"(mbar), "r"(parity) : "memory");
}

__device__ __forceinline__ void st_async_b64(uint32_t raddr, unsigned long long v,
                                             uint32_t rmbar) {
    asm volatile(
        "st.async.shared::cluster.mbarrier::complete_tx::bytes.b64 [%0], %1, [%2];"
        :: "r"(raddr), "l"(v), "r"(rmbar) : "memory");
}

__device__ __forceinline__ unsigned long long shfl_down16_b64(unsigned long long v) {
    unsigned lo = (unsigned)(v & 0xFFFFFFFFULL);
    unsigned hi = (unsigned)(v >> 32);
    lo = __shfl_down_sync(0xFFFFFFFFu, lo, 16);
    hi = __shfl_down_sync(0xFFFFFFFFu, hi, 16);
    return ((unsigned long long)hi << 32) | lo;
}

// ---------------------------------------------------------------------------
// FUSED RNN kernel: xWx + recurrence in ONE kernel.
//   16 clusters x 8 CTAs, 512 threads. Cluster owns 4 batch rows; CTA rank r
//   owns output columns [64r, 64r+64).
//   Weights: Wh slice register-resident (64 regs); Wx slice SMEM-resident
//   (128 KB, loaded once). x(t) tile (4x512, 8 KB) double-buffered in SMEM,
//   prefetched each step via 1 LDG.128/thread.
//   Per step: x-kloop (no peer dependency -> hides exchange flight) ->
//   wait my h chunk (chunked full barriers, R10) -> Wh-kloop into SAME
//   accumulators -> shfl pre-reduce -> STS -> one bar -> reduce + bias +
//   tanh -> STG + wait-free st.async broadcast (R10 causal chain).
// ---------------------------------------------------------------------------
#define CLUSTER       8
#define NCTA          128
#define BATCH_PER_CL  4
#define COLS_PER_CTA  64

// SMEM layout (float indices)
#define HBUF_ELEMS   (2 * BATCH_PER_CL * HH)             // 4096 (16 KB)
#define XBUF_ELEMS   (2 * BATCH_PER_CL * DD)             // 4096 (16 KB)
#define RED16_ELEMS  (16 * BATCH_PER_CL * COLS_PER_CTA)  // 4096 per buf
#define XBUF_OFF     HBUF_ELEMS                          // 4096
#define RED_OFF      (HBUF_ELEMS + XBUF_ELEMS)           // 8192
#define WXS_OFF      (RED_OFF + 2 * RED16_ELEMS)         // 16384 floats
#define WXS_U64      (DD * (COLS_PER_CTA / 2))           // 16384 u64 (128 KB)
#define MBAR_OFF     ((WXS_OFF + 2 * WXS_U64) * 4)       // 196608 bytes
#define MB_FULL(p, r) (MBAR_OFF + ((p) * 8 + (r)) * 8)
#define RNN_SMEM_BYTES (MBAR_OFF + 128)

#define CHUNK_TX_BYTES 1024   // 128 producer threads x 8 B land per peer chunk

__global__ __launch_bounds__(512, 1) __cluster_dims__(CLUSTER, 1, 1)
void rnn_fused_kernel(const float* __restrict__ X,     // [NB][TT][DD]
                      const float* __restrict__ h0,    // [NB][HH]
                      const float* __restrict__ Wx,    // [DD][HH]
                      const float* __restrict__ Wh,    // [HH][HH]
                      const float* __restrict__ bias,  // [HH]
                      float* __restrict__ out)         // [NB][TT][HH]
{
    extern __shared__ float smem[];
    float* hbuf = smem;                       // [2][4][HH]
    float* xbuf = smem + XBUF_OFF;            // [2][4][DD]
    float* red  = smem + RED_OFF;             // [2][16][4][64]
    unsigned long long* WxsU =
        reinterpret_cast<unsigned long long*>(smem + WXS_OFF); // [DD][32]

    const int tid = threadIdx.x;
    uint32_t rank;
    asm("mov.u32 %0, %%cluster_ctarank;" : "=r"(rank));
    const int cid = blockIdx.x >> 3;
    const int b0  = cid * BATCH_PER_CL;

    const int kq    = tid >> 4;          // 0..31
    const int cq    = tid & 15;          // 0..15
    const int kbase = kq * 16;
    const int kq2   = tid >> 5;          // warp id 0..15
    const int chunk = tid >> 6;          // 0..7: source rank my warp consumes
    const int jg0   = (int)rank * COLS_PER_CTA + cq * 4;

    // x prefetch mapping: each thread owns one float4 of the 4x512 x tile
    const int pb = tid >> 7;             // batch 0..3
    const int pk = (tid & 127) * 4;      // d offset
    const float* xsrc = X + ((size_t)(b0 + pb) * TT) * DD + pk;

    // ---- Wh slice -> registers (once) ----
    unsigned long long w01[16], w23[16];
#pragma unroll
    for (int kk = 0; kk < 16; ++kk) {
        ulonglong2 v = *reinterpret_cast<const ulonglong2*>(
            Wh + (size_t)(kbase + kk) * HH + jg0);
        w01[kk] = v.x;
        w23[kk] = v.y;
    }

    uint32_t smem_u32;
    asm("{ .reg .u64 t; cvta.to.shared.u64 t, %1; cvt.u32.u64 %0, t; }"
        : "=r"(smem_u32) : "l"(smem));

    // ---- init: mbarriers ----
    if (tid == 0) {
#pragma unroll
        for (int r = 0; r < CLUSTER; ++r) {
            MBAR_INIT(smem_u32 + MB_FULL(0, r), 1);
            MBAR_INIT(smem_u32 + MB_FULL(1, r), 1);
            MBAR_EXPECT_TX(smem_u32 + MB_FULL(0, r), CHUNK_TX_BYTES);
            MBAR_EXPECT_TX(smem_u32 + MB_FULL(1, r), CHUNK_TX_BYTES);
        }
    }
    // ---- h0 into buffer 0 ----
    for (int idx = tid; idx < BATCH_PER_CL * HH; idx += 512)
        hbuf[idx] = h0[(size_t)b0 * HH + idx];
    // ---- Wx column slice -> SMEM (once): WxsU[d][c2] = Wx[d][jgbase+2c2..+1]
    {
        const int jgbase = (int)rank * COLS_PER_CTA;
        const unsigned long long* wsrc =
            reinterpret_cast<const unsigned long long*>(Wx + jgbase);
        for (int idx = tid; idx < DD * 32; idx += 512) {
            int d  = idx >> 5;
            int c2 = idx & 31;
            WxsU[d * 32 + c2] = wsrc[(size_t)d * (HH / 2) + c2];
        }
    }
    // ---- x(0) into xbuf[0] ----
    *reinterpret_cast<float4*>(&xbuf[pb * DD + pk]) =
        *reinterpret_cast<const float4*>(xsrc);
    __syncthreads();
    asm volatile("barrier.cluster.arrive.aligned;\n\t"
                 "barrier.cluster.wait.aligned;" ::: "memory");

    // peer smem base addresses (mapa once)
    uint32_t rbase[CLUSTER];
#pragma unroll
    for (int p = 0; p < CLUSTER; ++p)
        asm("mapa.shared::cluster.u32 %0, %1, %2;"
            : "=r"(rbase[p]) : "r"(smem_u32), "r"(p));

    // output-stage mapping (threads < 256)
    const int fb = (tid >> 6) & 3;
    const int fc = tid & 63;
    const int jg = (int)rank * COLS_PER_CTA + fc;
    float* outp = out + ((size_t)(b0 + fb) * TT) * HH + jg;
    const bool is_red   = (tid < 256);
    const bool is_store = (tid < 256) && ((tid & 1) == 0);
    const bool is_arm   = ((tid & 63) == 0);   // one re-armer per chunk
    const bool is_lo    = ((tid & 16) == 0);   // lane < 16 within warp

    float bb = 0.0f;
    if (is_red) bb = bias[jg];

    int pf[2] = {0, 0};   // per-warp parity for full[buf][chunk]

#pragma unroll 2
    for (int t = 0; t < TT; ++t) {
        const int p = t & 1;
        const int q = p ^ 1;

        // prefetch x(t+1) into registers (stored to xbuf[q] before the bar)
        float4 xnext = make_float4(0.f, 0.f, 0.f, 0.f);
        if (t + 1 < TT)
            xnext = *reinterpret_cast<const float4*>(xsrc + (size_t)(t + 1) * DD);

        unsigned long long a01[4] = {0ULL, 0ULL, 0ULL, 0ULL};
        unsigned long long a23[4] = {0ULL, 0ULL, 0ULL, 0ULL};

        // ===== x-kloop: acc += Wx^T x(t); no peer dependency — runs while
        // the peers' h-chunk exchange is still in flight =====
        {
            const float* xc = xbuf + p * (BATCH_PER_CL * DD);
#pragma unroll
            for (int kk4 = 0; kk4 < 4; ++kk4) {
                const int k = kbase + kk4 * 4;
                ulonglong2 wv0 = *reinterpret_cast<const ulonglong2*>(
                    &WxsU[(size_t)(k + 0) * 32 + 2 * cq]);
                ulonglong2 wv1 = *reinterpret_cast<const ulonglong2*>(
                    &WxsU[(size_t)(k + 1) * 32 + 2 * cq]);
                ulonglong2 wv2 = *reinterpret_cast<const ulonglong2*>(
                    &WxsU[(size_t)(k + 2) * 32 + 2 * cq]);
                ulonglong2 wv3 = *reinterpret_cast<const ulonglong2*>(
                    &WxsU[(size_t)(k + 3) * 32 + 2 * cq]);
#pragma unroll
                for (int b = 0; b < 4; ++b) {
                    float4 xv = *reinterpret_cast<const float4*>(&xc[b * DD + k]);
                    unsigned long long hh;
                    hh = pack_dup(xv.x);
                    ffma2(a01[b], hh, wv0.x);
                    ffma2(a23[b], hh, wv0.y);
                    hh = pack_dup(xv.y);
                    ffma2(a01[b], hh, wv1.x);
                    ffma2(a23[b], hh, wv1.y);
                    hh = pack_dup(xv.z);
                    ffma2(a01[b], hh, wv2.x);
                    ffma2(a23[b], hh, wv2.y);
                    hh = pack_dup(xv.w);
                    ffma2(a01[b], hh, wv3.x);
                    ffma2(a23[b], hh, wv3.y);
                }
            }
        }

        // ===== wait only for MY chunk of h_t; elected thread re-arms =====
        if (t > 0) {
            mbar_wait_parity(smem_u32 + MB_FULL(p, chunk), (uint32_t)pf[p]);
            pf[p] ^= 1;
            if (is_arm)
                MBAR_EXPECT_TX(smem_u32 + MB_FULL(p, chunk), CHUNK_TX_BYTES);
        }

        // ===== Wh-kloop: acc += Wh^T h(t) (weights in registers) =====
        {
            const float* hc = hbuf + p * (BATCH_PER_CL * HH);
#pragma unroll
            for (int kk4 = 0; kk4 < 4; ++kk4) {
                const int k = kbase + kk4 * 4;
#pragma unroll
                for (int b = 0; b < 4; ++b) {
                    float4 hv = *reinterpret_cast<const float4*>(&hc[b * HH + k]);
                    unsigned long long hh;
                    hh = pack_dup(hv.x);
                    ffma2(a01[b], hh, w01[kk4 * 4 + 0]);
                    ffma2(a23[b], hh, w23[kk4 * 4 + 0]);
                    hh = pack_dup(hv.y);
                    ffma2(a01[b], hh, w01[kk4 * 4 + 1]);
                    ffma2(a23[b], hh, w23[kk4 * 4 + 1]);
                    hh = pack_dup(hv.z);
                    ffma2(a01[b], hh, w01[kk4 * 4 + 2]);
                    ffma2(a23[b], hh, w23[kk4 * 4 + 2]);
                    hh = pack_dup(hv.w);
                    ffma2(a01[b], hh, w01[kk4 * 4 + 3]);
                    ffma2(a23[b], hh, w23[kk4 * 4 + 3]);
                }
            }
        }

        // warp pre-reduce: lane L += lane L+16 (kq pair, same cols)
#pragma unroll
        for (int b = 0; b < 4; ++b) {
            a01[b] = add2(a01[b], shfl_down16_b64(a01[b]));
            a23[b] = add2(a23[b], shfl_down16_b64(a23[b]));
        }

        // pre-reduced partials -> red[p][kq2][b][4cq..4cq+3] (lanes < 16)
        float* rp = red + p * RED16_ELEMS;
        if (is_lo) {
#pragma unroll
            for (int b = 0; b < 4; ++b) {
                ulonglong2 v;
                v.x = a01[b];
                v.y = a23[b];
                *reinterpret_cast<ulonglong2*>(
                    &rp[(kq2 * BATCH_PER_CL + b) * COLS_PER_CTA + cq * 4]) = v;
            }
        }

        // stage x(t+1) into xbuf[q] (readers of xbuf[q] come after bar(t))
        if (t + 1 < TT)
            *reinterpret_cast<float4*>(&xbuf[q * (BATCH_PER_CL * DD) + pb * DD + pk]) = xnext;

        __syncthreads();   // the ONLY block barrier per step

        if (is_red) {
            // 16-way reduce, 4 parallel chains; seed with bias
            float s0 = bb, s1 = 0.f, s2 = 0.f, s3 = 0.f;
#pragma unroll
            for (int qd = 0; qd < 4; ++qd) {
                s0 += rp[((4 * qd + 0) * BATCH_PER_CL + fb) * COLS_PER_CTA + fc];
                s1 += rp[((4 * qd + 1) * BATCH_PER_CL + fb) * COLS_PER_CTA + fc];
                s2 += rp[((4 * qd + 2) * BATCH_PER_CL + fb) * COLS_PER_CTA + fc];
                s3 += rp[((4 * qd + 3) * BATCH_PER_CL + fb) * COLS_PER_CTA + fc];
            }
            float s = (s0 + s1) + (s2 + s3);
            float r;
            asm("tanh.approx.f32 %0, %1;" : "=f"(r) : "f"(s));
            outp[(size_t)t * HH] = r;

            if (t + 1 < TT) {
                // WAIT-FREE store (R10 causal chain: buffer-q readers are
                // ordered behind us via the full-barrier chain).
                float rn = __shfl_down_sync(0xFFFFFFFFu, r, 1);
                if (is_store) {
                    unsigned long long v = pack2(r, rn);
                    const uint32_t off =
                        (uint32_t)((q * BATCH_PER_CL + fb) * HH + jg) * 4u;
                    const uint32_t mboff = (uint32_t)MB_FULL(q, (int)rank);
#pragma unroll
                    for (int pp = 0; pp < CLUSTER; ++pp)
                        st_async_b64(rbase[pp] + off, v, rbase[pp] + mboff);
                }
            }
        }
        // no trailing barrier: red double-buffered; cross-step ordering
        // guaranteed by bar(t) between reduce-read(t-1) and STS(t+1).
    }

    // drain before exit
    asm volatile("barrier.cluster.arrive.aligned;\n\t"
                 "barrier.cluster.wait.aligned;" ::: "memory");
}

// ---------------------------------------------------------------------------
// Launch: single fused kernel; out is write-only.
// ---------------------------------------------------------------------------
extern "C" void kernel_launch(void* const* d_in, const int* in_sizes, int n_in,
                              void* d_out, int out_size) {
    const float* x  = (const float*)d_in[0];
    const float* h0 = (const float*)d_in[1];
    const float* Wx = (const float*)d_in[2];
    const float* Wh = (const float*)d_in[3];
    const float* b  = (const float*)d_in[4];
    float* out = (float*)d_out;

    (void)in_sizes; (void)n_in; (void)out_size;

    cudaFuncSetAttribute(rnn_fused_kernel,
                         cudaFuncAttributeMaxDynamicSharedMemorySize,
                         RNN_SMEM_BYTES);
    rnn_fused_kernel<<<NCTA, 512, RNN_SMEM_BYTES>>>(x, h0, Wx, Wh, b, out);
}

// round 15
// speedup vs baseline: 1.0700x; 1.0700x over previous
#include <cuda_runtime.h>
#include <cuda_bf16.h>
#include <math.h>
#include <stdint.h>

// Problem constants: N=64, T=512, D=512, H=512, fp32
#define NB   64
#define TT   512
#define DD   512
#define HH   512
#define MM   (NB * TT)

// ---------------------------------------------------------------------------
// f32x2 packed-math helpers
// ---------------------------------------------------------------------------
__device__ __forceinline__ void ffma2(unsigned long long& acc,
                                      unsigned long long a,
                                      unsigned long long b) {
    asm("fma.rn.f32x2 %0, %1, %2, %0;" : "+l"(acc) : "l"(a), "l"(b));
}
__device__ __forceinline__ unsigned long long add2(unsigned long long a,
                                                   unsigned long long b) {
    unsigned long long r;
    asm("add.rn.f32x2 %0, %1, %2;" : "=l"(r) : "l"(a), "l"(b));
    return r;
}
__device__ __forceinline__ unsigned long long pack_dup(float v) {
    unsigned long long r;
    unsigned u = __float_as_uint(v);
    asm("mov.b64 %0, {%1, %1};" : "=l"(r) : "r"(u));
    return r;
}

// mbarrier helpers -----------------------------------------------------------
#define MBAR_INIT(addr, cnt) \
    asm volatile("mbarrier.init.shared.b64 [%0], %1;" :: "r"(addr), "r"(cnt) : "memory")
#define MBAR_EXPECT_TX(addr, bytes) \
    asm volatile("mbarrier.arrive.expect_tx.shared.b64 _, [%0], %1;" \
                 :: "r"(addr), "r"(bytes) : "memory")

__device__ __forceinline__ void mbar_wait_parity(uint32_t mbar, uint32_t parity) {
    asm volatile(
        "{\n\t"
        ".reg .pred P;\n\t"
        "WL_%=:\n\t"
        "mbarrier.try_wait.parity.acquire.cluster.shared::cta.b64 P, [%0], %1, 0x989680;\n\t"
        "@P bra WD_%=;\n\t"
        "bra WL_%=;\n\t"
        "WD_%=:\n\t"
        "}" :: "r"(mbar), "r"(parity) : "memory");
}

__device__ __forceinline__ void st_async_b64(uint32_t raddr, unsigned long long v,
                                             uint32_t rmbar) {
    asm volatile(
        "st.async.shared::cluster.mbarrier::complete_tx::bytes.b64 [%0], %1, [%2];"
        :: "r"(raddr), "l"(v), "r"(rmbar) : "memory");
}

// ---------------------------------------------------------------------------
// Kernel A: xwx = x @ Wx + b  (into d_out), FFMA2 SGEMM — R12 version
// (BK=16, double-buffered SMEM + register prefetch, 2 CTAs/SM).
// ---------------------------------------------------------------------------
#define BM 128
#define BN 128
#define BK 16
#define KITERS (DD / BK)   // 32

__global__ __launch_bounds__(256, 2) void gemm_xwx_kernel(
    const float* __restrict__ X,
    const float* __restrict__ Wx,
    const float* __restrict__ bias,
    float* __restrict__ out)
{
    __shared__ float2 Asd[2][BK][BM];
    __shared__ float  Bs[2][BK][BN];

    const int tid = threadIdx.x;
    const int m0 = blockIdx.y * BM;
    const int n0 = blockIdx.x * BN;

    const int arow = tid >> 1;
    const int acol = (tid & 1) * 8;
    const int brow = tid >> 4;
    const int bcol = (tid & 15) * 8;

    const int ty = tid >> 4;
    const int tx = tid & 15;

    const float* aptr = X + (size_t)(m0 + arow) * DD + acol;
    const float* bptr = Wx + (size_t)brow * HH + n0 + bcol;

    unsigned long long acc2[8][4];
#pragma unroll
    for (int i = 0; i < 8; ++i)
#pragma unroll
        for (int j = 0; j < 4; ++j) acc2[i][j] = 0ULL;

    float4 av0 = *reinterpret_cast<const float4*>(aptr);
    float4 av1 = *reinterpret_cast<const float4*>(aptr + 4);
    float4 bv0 = *reinterpret_cast<const float4*>(bptr);
    float4 bv1 = *reinterpret_cast<const float4*>(bptr + 4);
    {
        Asd[0][acol + 0][arow] = make_float2(av0.x, av0.x);
        Asd[0][acol + 1][arow] = make_float2(av0.y, av0.y);
        Asd[0][acol + 2][arow] = make_float2(av0.z, av0.z);
        Asd[0][acol + 3][arow] = make_float2(av0.w, av0.w);
        Asd[0][acol + 4][arow] = make_float2(av1.x, av1.x);
        Asd[0][acol + 5][arow] = make_float2(av1.y, av1.y);
        Asd[0][acol + 6][arow] = make_float2(av1.z, av1.z);
        Asd[0][acol + 7][arow] = make_float2(av1.w, av1.w);
        *reinterpret_cast<float4*>(&Bs[0][brow][bcol])     = bv0;
        *reinterpret_cast<float4*>(&Bs[0][brow][bcol + 4]) = bv1;
    }
    __syncthreads();

    for (int it = 0; it < KITERS; ++it) {
        const int cur = it & 1;
        const int nxt = cur ^ 1;

        if (it + 1 < KITERS) {
            const float* ap = aptr + (it + 1) * BK;
            const float* bp = bptr + (size_t)(it + 1) * BK * HH;
            av0 = *reinterpret_cast<const float4*>(ap);
            av1 = *reinterpret_cast<const float4*>(ap + 4);
            bv0 = *reinterpret_cast<const float4*>(bp);
            bv1 = *reinterpret_cast<const float4*>(bp + 4);
        }

#pragma unroll
        for (int k = 0; k < BK; ++k) {
            unsigned long long a2[8], b2[4];
            ulonglong2 t0 = *reinterpret_cast<const ulonglong2*>(&Bs[cur][k][tx * 8]);
            ulonglong2 t1 = *reinterpret_cast<const ulonglong2*>(&Bs[cur][k][tx * 8 + 4]);
            b2[0] = t0.x; b2[1] = t0.y; b2[2] = t1.x; b2[3] = t1.y;
#pragma unroll
            for (int i = 0; i < 8; ++i)
                a2[i] = *reinterpret_cast<const unsigned long long*>(&Asd[cur][k][ty * 8 + i]);
#pragma unroll
            for (int i = 0; i < 8; ++i)
#pragma unroll
                for (int j = 0; j < 4; ++j)
                    ffma2(acc2[i][j], a2[i], b2[j]);
        }

        if (it + 1 < KITERS) {
            Asd[nxt][acol + 0][arow] = make_float2(av0.x, av0.x);
            Asd[nxt][acol + 1][arow] = make_float2(av0.y, av0.y);
            Asd[nxt][acol + 2][arow] = make_float2(av0.z, av0.z);
            Asd[nxt][acol + 3][arow] = make_float2(av0.w, av0.w);
            Asd[nxt][acol + 4][arow] = make_float2(av1.x, av1.x);
            Asd[nxt][acol + 5][arow] = make_float2(av1.y, av1.y);
            Asd[nxt][acol + 6][arow] = make_float2(av1.z, av1.z);
            Asd[nxt][acol + 7][arow] = make_float2(av1.w, av1.w);
            *reinterpret_cast<float4*>(&Bs[nxt][brow][bcol])     = bv0;
            *reinterpret_cast<float4*>(&Bs[nxt][brow][bcol + 4]) = bv1;
        }
        __syncthreads();
    }

    unsigned long long bb2[4];
    {
        ulonglong2 t0 = *reinterpret_cast<const ulonglong2*>(bias + n0 + tx * 8);
        ulonglong2 t1 = *reinterpret_cast<const ulonglong2*>(bias + n0 + tx * 8 + 4);
        bb2[0] = t0.x; bb2[1] = t0.y; bb2[2] = t1.x; bb2[3] = t1.y;
    }
#pragma unroll
    for (int i = 0; i < 8; ++i) {
        float* orow = out + (size_t)(m0 + ty * 8 + i) * HH + n0 + tx * 8;
        ulonglong2 v0, v1;
        v0.x = add2(acc2[i][0], bb2[0]);
        v0.y = add2(acc2[i][1], bb2[1]);
        v1.x = add2(acc2[i][2], bb2[2]);
        v1.y = add2(acc2[i][3], bb2[3]);
        *reinterpret_cast<ulonglong2*>(orow)     = v0;
        *reinterpret_cast<ulonglong2*>(orow + 4) = v1;
    }
}

// ---------------------------------------------------------------------------
// Kernel B: POINT-TO-POINT ACCUMULATE recurrence.
//   16 clusters x 8 CTAs, 256 threads. Cluster owns 4 batch rows.
//   CTA rank r: owns output cols [64r,64r+64) AND k-chunk [64r,64r+64) —
//   identical ranges, so h is produced exactly where it is consumed next
//   step: NO h broadcast exists.
//   Thread t: cols {2t, 2t+1} (all 512 cols covered), k = local chunk.
//   Per step (uniform, no t-conditionals):
//     kloop: acc[b] += {h_b,h_b} x {w_c0,w_c1} over 64 local k
//            (h stored DUPLICATED locally -> zero pack MOVs; LDS.128 is
//             full-warp broadcast)
//     send:  4x st.async.b64 of COMPLETE partials to owner's slot[p]
//     wait:  my slot[p] mbar (expect_tx 8 KB = 8 src x 1 KB); elected rearm
//     reduce: 8 scalar LDS + xwx + bias -> tanh -> STG out; STS hloc[q]{r,r}
//     one __syncthreads.
//   Safety (R10 causal chain): read-slot[p](t-2) < bar(t-2) < send(t-1) <
//   peer-wait(t-1) < peer-send(t -> slot[p]); rearm(t) < send(t+1) <
//   peer-wait(t+1) < peer-send(t+2 -> mbar[p]). Slots are fully overwritten
//   each use (write-once per phase) -> no zeroing needed.
// ---------------------------------------------------------------------------
#define CLUSTER       8
#define NCTA          128
#define BATCH_PER_CL  4

// smem layout (bytes):
//   [0, 4096)        hloc: [2 buf][64 k][4 b] u64 {h,h}
//   [4096, 20480)    slot: [2 buf][8 src][4 b][32 colpair] u64
//   [20480, 20496)   mbar[2]
#define HLOC_B   0
#define SLOT_B   4096
#define MBAR_B   20480
#define RNN_SMEM_BYTES 20496
#define SLOT_TX  8192     // 8 src CTAs x 256 thr-slots... = 8*4*32*8 bytes

__global__ __launch_bounds__(256, 1) __cluster_dims__(CLUSTER, 1, 1)
void rnn_p2p_kernel(const float* __restrict__ h0,
                    const float* __restrict__ Wh,
                    const float* __restrict__ bias,
                    float* __restrict__ out)
{
    extern __shared__ float smem[];
    unsigned long long* hlocU = reinterpret_cast<unsigned long long*>(smem);
    float* slotF = smem + SLOT_B / 4;

    const int tid = threadIdx.x;
    uint32_t rank;
    asm("mov.u32 %0, %%cluster_ctarank;" : "=r"(rank));
    const int cid = blockIdx.x >> 3;
    const int b0  = cid * BATCH_PER_CL;

    // kloop mapping: thread t -> global cols {2t, 2t+1}
    const int owner = tid >> 5;          // owner CTA of my cols
    const int cp    = tid & 31;          // col-pair index within owner block
    const int kg0   = (int)rank * 64;    // my k-chunk base

    // ---- Wh slice -> registers (once): w[kk] = {Wh[kg0+kk][2t], [2t+1]} ----
    unsigned long long w[64];
#pragma unroll
    for (int kk = 0; kk < 64; ++kk)
        w[kk] = *reinterpret_cast<const unsigned long long*>(
            Wh + (size_t)(kg0 + kk) * HH + 2 * tid);

    uint32_t smem_u32;
    asm("{ .reg .u64 t; cvta.to.shared.u64 t, %1; cvt.u32.u64 %0, t; }"
        : "=r"(smem_u32) : "l"(smem));
    const uint32_t mb[2] = {smem_u32 + MBAR_B, smem_u32 + MBAR_B + 8};

    // ---- init: mbarriers (pre-armed both) + hloc[0] from h0 (duplicated) ----
    if (tid == 0) {
        MBAR_INIT(mb[0], 1);
        MBAR_INIT(mb[1], 1);
        MBAR_EXPECT_TX(mb[0], SLOT_TX);
        MBAR_EXPECT_TX(mb[1], SLOT_TX);
    }
    {
        const int kk = tid >> 2;        // 0..63
        const int bb = tid & 3;         // 0..3
        float v = h0[(size_t)(b0 + bb) * HH + kg0 + kk];
        hlocU[(size_t)kk * 4 + bb] = pack_dup(v);
    }
    __syncthreads();
    asm volatile("barrier.cluster.arrive.aligned;\n\t"
                 "barrier.cluster.wait.aligned;" ::: "memory");

    // peer smem base addresses (mapa once)
    uint32_t rbase[CLUSTER];
#pragma unroll
    for (int p = 0; p < CLUSTER; ++p)
        asm("mapa.shared::cluster.u32 %0, %1, %2;"
            : "=r"(rbase[p]) : "r"(smem_u32), "r"(p));

    // reduce/output mapping: thread u -> batch rb, local col rc
    const int rb = tid >> 6;             // 0..3
    const int rc = tid & 63;             // 0..63 (== local k index next step)
    float* outp = out + ((size_t)(b0 + rb) * TT) * HH + (int)rank * 64 + rc;
    const float bb_bias = bias[(int)rank * 64 + rc];

    // send address bases (owner fixed per thread)
    const uint32_t send_base0 =
        rbase[owner] + SLOT_B + ((uint32_t)((int)rank * 4) * 32 + cp) * 8;
    const uint32_t send_mb0 = rbase[owner] + MBAR_B;
    // per-buffer offsets: slot buf stride = 8*4*32*8 = 8192 B; mbar stride 8 B

    int pf[2] = {0, 0};

    for (int t = 0; t < TT; ++t) {
        const int p = t & 1;
        const int q = p ^ 1;

        // prefetch xwx(t) (consumed after the wait; latency hidden by kloop)
        float xw = outp[(size_t)t * HH];

        // ===== kloop: complete partials over my local k-chunk =====
        unsigned long long acc0 = 0ULL, acc1 = 0ULL, acc2v = 0ULL, acc3 = 0ULL;
        const unsigned long long* hl = hlocU + p * 256;
#pragma unroll
        for (int kk = 0; kk < 64; ++kk) {
            ulonglong2 h01 = *reinterpret_cast<const ulonglong2*>(hl + kk * 4);
            ulonglong2 h23 = *reinterpret_cast<const ulonglong2*>(hl + kk * 4 + 2);
            ffma2(acc0, h01.x, w[kk]);
            ffma2(acc1, h01.y, w[kk]);
            ffma2(acc2v, h23.x, w[kk]);
            ffma2(acc3, h23.y, w[kk]);
        }

        // ===== send complete partials point-to-point to owner's slot[p] =====
        {
            const uint32_t sb = send_base0 + (uint32_t)p * 8192u;
            const uint32_t sm = send_mb0 + (uint32_t)p * 8u;
            st_async_b64(sb + 0u * 256u, acc0, sm);
            st_async_b64(sb + 1u * 256u, acc1, sm);
            st_async_b64(sb + 2u * 256u, acc2v, sm);
            st_async_b64(sb + 3u * 256u, acc3, sm);
        }

        // ===== wait my slot[p] (8 KB from 8 sources); elected rearm =====
        mbar_wait_parity(mb[p], (uint32_t)pf[p]);
        pf[p] ^= 1;
        if (tid == 0) MBAR_EXPECT_TX(mb[p], SLOT_TX);

        // ===== reduce 8 source partials + xwx + bias -> tanh =====
        {
            const float* sf = slotF + p * 2048;   // [8 src][4 b][64 floats]
            float s0 = xw + bb_bias, s1 = 0.f, s2 = 0.f, s3 = 0.f;
            const int fo = rb * 64 + rc;
            s0 += sf[0 * 256 + fo];
            s1 += sf[1 * 256 + fo];
            s2 += sf[2 * 256 + fo];
            s3 += sf[3 * 256 + fo];
            s0 += sf[4 * 256 + fo];
            s1 += sf[5 * 256 + fo];
            s2 += sf[6 * 256 + fo];
            s3 += sf[7 * 256 + fo];
            float s = (s0 + s1) + (s2 + s3);
            float r;
            asm("tanh.approx.f32 %0, %1;" : "=f"(r) : "f"(s));

            outp[(size_t)t * HH] = r;
            // h for next step, duplicated, stored LOCALLY (rc == local k)
            hlocU[(size_t)q * 256 + rc * 4 + rb] = pack_dup(r);
        }
        __syncthreads();   // hloc[q] complete before next step's kloop
    }

    // drain before exit (in-flight st.async of last step already consumed
    // by the last wait; barrier protects smem lifetime across cluster)
    asm volatile("barrier.cluster.arrive.aligned;\n\t"
                 "barrier.cluster.wait.aligned;" ::: "memory");
}

// ---------------------------------------------------------------------------
// Launch
// ---------------------------------------------------------------------------
extern "C" void kernel_launch(void* const* d_in, const int* in_sizes, int n_in,
                              void* d_out, int out_size) {
    const float* x  = (const float*)d_in[0];
    const float* h0 = (const float*)d_in[1];
    const float* Wx = (const float*)d_in[2];
    const float* Wh = (const float*)d_in[3];
    const float* b  = (const float*)d_in[4];
    float* out = (float*)d_out;

    (void)in_sizes; (void)n_in; (void)out_size;

    // Stage 1: xwx = x @ Wx + b, into out (scratch).
    dim3 gridA(HH / BN, MM / BM);
    gemm_xwx_kernel<<<gridA, 256>>>(x, Wx, b, out);

    // Stage 2: point-to-point accumulate recurrence.
    cudaFuncSetAttribute(rnn_p2p_kernel,
                         cudaFuncAttributeMaxDynamicSharedMemorySize,
                         RNN_SMEM_BYTES);
    rnn_p2p_kernel<<<NCTA, 256, RNN_SMEM_BYTES>>>(h0, Wh, b, out);
}

// round 16
// speedup vs baseline: 1.2612x; 1.1787x over previous
#include <cuda_runtime.h>
#include <cuda_bf16.h>
#include <math.h>
#include <stdint.h>

// Problem constants: N=64, T=512, D=512, H=512, fp32
#define NB   64
#define TT   512
#define DD   512
#define HH   512
#define MM   (NB * TT)

// ---------------------------------------------------------------------------
// f32x2 packed-math helpers
// ---------------------------------------------------------------------------
__device__ __forceinline__ void ffma2(unsigned long long& acc,
                                      unsigned long long a,
                                      unsigned long long b) {
    asm("fma.rn.f32x2 %0, %1, %2, %0;" : "+l"(acc) : "l"(a), "l"(b));
}
__device__ __forceinline__ unsigned long long add2(unsigned long long a,
                                                   unsigned long long b) {
    unsigned long long r;
    asm("add.rn.f32x2 %0, %1, %2;" : "=l"(r) : "l"(a), "l"(b));
    return r;
}
__device__ __forceinline__ unsigned long long pack_dup(float v) {
    unsigned long long r;
    unsigned u = __float_as_uint(v);
    asm("mov.b64 %0, {%1, %1};" : "=l"(r) : "r"(u));
    return r;
}
__device__ __forceinline__ unsigned long long pack2(float lo, float hi) {
    unsigned long long r;
    asm("mov.b64 %0, {%1, %2};" : "=l"(r) : "f"(lo), "f"(hi));
    return r;
}

// mbarrier helpers -----------------------------------------------------------
#define MBAR_INIT(addr, cnt) \
    asm volatile("mbarrier.init.shared.b64 [%0], %1;" :: "r"(addr), "r"(cnt) : "memory")
#define MBAR_EXPECT_TX(addr, bytes) \
    asm volatile("mbarrier.arrive.expect_tx.shared.b64 _, [%0], %1;" \
                 :: "r"(addr), "r"(bytes) : "memory")

__device__ __forceinline__ void mbar_wait_parity(uint32_t mbar, uint32_t parity) {
    asm volatile(
        "{\n\t"
        ".reg .pred P;\n\t"
        "WL_%=:\n\t"
        "mbarrier.try_wait.parity.acquire.cluster.shared::cta.b64 P, [%0], %1, 0x989680;\n\t"
        "@P bra WD_%=;\n\t"
        "bra WL_%=;\n\t"
        "WD_%=:\n\t"
        "}" :: "r"(mbar), "r"(parity) : "memory");
}

__device__ __forceinline__ void st_async_b64(uint32_t raddr, unsigned long long v,
                                             uint32_t rmbar) {
    asm volatile(
        "st.async.shared::cluster.mbarrier::complete_tx::bytes.b64 [%0], %1, [%2];"
        :: "r"(raddr), "l"(v), "r"(rmbar) : "memory");
}

__device__ __forceinline__ unsigned long long shfl_down16_b64(unsigned long long v) {
    unsigned lo = (unsigned)(v & 0xFFFFFFFFULL);
    unsigned hi = (unsigned)(v >> 32);
    lo = __shfl_down_sync(0xFFFFFFFFu, lo, 16);
    hi = __shfl_down_sync(0xFFFFFFFFu, hi, 16);
    return ((unsigned long long)hi << 32) | lo;
}

// ---------------------------------------------------------------------------
// Kernel A: xwx = x @ Wx + b  (into d_out), FFMA2 SGEMM.
//   R12 structure (BK=16, double-buffered SMEM + register prefetch,
//   2 CTAs/SM) + NEW: A-values loaded with 4x LDS.128 instead of 8x LDS.64
//   (LDS slots per k-step: 10 -> 6; issue overhead 31% -> 19%).
// ---------------------------------------------------------------------------
#define BM 128
#define BN 128
#define BK 16
#define KITERS (DD / BK)   // 32

__global__ __launch_bounds__(256, 2) void gemm_xwx_kernel(
    const float* __restrict__ X,
    const float* __restrict__ Wx,
    const float* __restrict__ bias,
    float* __restrict__ out)
{
    __shared__ float2 Asd[2][BK][BM];   // duplicated A: {a,a}; 2 buffers
    __shared__ float  Bs[2][BK][BN];

    const int tid = threadIdx.x;
    const int m0 = blockIdx.y * BM;
    const int n0 = blockIdx.x * BN;

    const int arow = tid >> 1;
    const int acol = (tid & 1) * 8;
    const int brow = tid >> 4;
    const int bcol = (tid & 15) * 8;

    const int ty = tid >> 4;
    const int tx = tid & 15;

    const float* aptr = X + (size_t)(m0 + arow) * DD + acol;
    const float* bptr = Wx + (size_t)brow * HH + n0 + bcol;

    unsigned long long acc2[8][4];
#pragma unroll
    for (int i = 0; i < 8; ++i)
#pragma unroll
        for (int j = 0; j < 4; ++j) acc2[i][j] = 0ULL;

    float4 av0 = *reinterpret_cast<const float4*>(aptr);
    float4 av1 = *reinterpret_cast<const float4*>(aptr + 4);
    float4 bv0 = *reinterpret_cast<const float4*>(bptr);
    float4 bv1 = *reinterpret_cast<const float4*>(bptr + 4);
    {
        Asd[0][acol + 0][arow] = make_float2(av0.x, av0.x);
        Asd[0][acol + 1][arow] = make_float2(av0.y, av0.y);
        Asd[0][acol + 2][arow] = make_float2(av0.z, av0.z);
        Asd[0][acol + 3][arow] = make_float2(av0.w, av0.w);
        Asd[0][acol + 4][arow] = make_float2(av1.x, av1.x);
        Asd[0][acol + 5][arow] = make_float2(av1.y, av1.y);
        Asd[0][acol + 6][arow] = make_float2(av1.z, av1.z);
        Asd[0][acol + 7][arow] = make_float2(av1.w, av1.w);
        *reinterpret_cast<float4*>(&Bs[0][brow][bcol])     = bv0;
        *reinterpret_cast<float4*>(&Bs[0][brow][bcol + 4]) = bv1;
    }
    __syncthreads();

    for (int it = 0; it < KITERS; ++it) {
        const int cur = it & 1;
        const int nxt = cur ^ 1;

        if (it + 1 < KITERS) {
            const float* ap = aptr + (it + 1) * BK;
            const float* bp = bptr + (size_t)(it + 1) * BK * HH;
            av0 = *reinterpret_cast<const float4*>(ap);
            av1 = *reinterpret_cast<const float4*>(ap + 4);
            bv0 = *reinterpret_cast<const float4*>(bp);
            bv1 = *reinterpret_cast<const float4*>(bp + 4);
        }

#pragma unroll
        for (int k = 0; k < BK; ++k) {
            unsigned long long a2[8], b2[4];
            // A: 4x LDS.128 (contiguous duplicated float2 pairs, 64B aligned)
            ulonglong2 aa0 = *reinterpret_cast<const ulonglong2*>(&Asd[cur][k][ty * 8]);
            ulonglong2 aa1 = *reinterpret_cast<const ulonglong2*>(&Asd[cur][k][ty * 8 + 2]);
            ulonglong2 aa2 = *reinterpret_cast<const ulonglong2*>(&Asd[cur][k][ty * 8 + 4]);
            ulonglong2 aa3 = *reinterpret_cast<const ulonglong2*>(&Asd[cur][k][ty * 8 + 6]);
            a2[0] = aa0.x; a2[1] = aa0.y;
            a2[2] = aa1.x; a2[3] = aa1.y;
            a2[4] = aa2.x; a2[5] = aa2.y;
            a2[6] = aa3.x; a2[7] = aa3.y;
            // B: 2x LDS.128
            ulonglong2 t0 = *reinterpret_cast<const ulonglong2*>(&Bs[cur][k][tx * 8]);
            ulonglong2 t1 = *reinterpret_cast<const ulonglong2*>(&Bs[cur][k][tx * 8 + 4]);
            b2[0] = t0.x; b2[1] = t0.y; b2[2] = t1.x; b2[3] = t1.y;
#pragma unroll
            for (int i = 0; i < 8; ++i)
#pragma unroll
                for (int j = 0; j < 4; ++j)
                    ffma2(acc2[i][j], a2[i], b2[j]);
        }

        if (it + 1 < KITERS) {
            Asd[nxt][acol + 0][arow] = make_float2(av0.x, av0.x);
            Asd[nxt][acol + 1][arow] = make_float2(av0.y, av0.y);
            Asd[nxt][acol + 2][arow] = make_float2(av0.z, av0.z);
            Asd[nxt][acol + 3][arow] = make_float2(av0.w, av0.w);
            Asd[nxt][acol + 4][arow] = make_float2(av1.x, av1.x);
            Asd[nxt][acol + 5][arow] = make_float2(av1.y, av1.y);
            Asd[nxt][acol + 6][arow] = make_float2(av1.z, av1.z);
            Asd[nxt][acol + 7][arow] = make_float2(av1.w, av1.w);
            *reinterpret_cast<float4*>(&Bs[nxt][brow][bcol])     = bv0;
            *reinterpret_cast<float4*>(&Bs[nxt][brow][bcol + 4]) = bv1;
        }
        __syncthreads();
    }

    unsigned long long bb2[4];
    {
        ulonglong2 t0 = *reinterpret_cast<const ulonglong2*>(bias + n0 + tx * 8);
        ulonglong2 t1 = *reinterpret_cast<const ulonglong2*>(bias + n0 + tx * 8 + 4);
        bb2[0] = t0.x; bb2[1] = t0.y; bb2[2] = t1.x; bb2[3] = t1.y;
    }
#pragma unroll
    for (int i = 0; i < 8; ++i) {
        float* orow = out + (size_t)(m0 + ty * 8 + i) * HH + n0 + tx * 8;
        ulonglong2 v0, v1;
        v0.x = add2(acc2[i][0], bb2[0]);
        v0.y = add2(acc2[i][1], bb2[1]);
        v1.x = add2(acc2[i][2], bb2[2]);
        v1.y = add2(acc2[i][3], bb2[3]);
        *reinterpret_cast<ulonglong2*>(orow)     = v0;
        *reinterpret_cast<ulonglong2*>(orow + 4) = v1;
    }
}

// ---------------------------------------------------------------------------
// Kernel B: cluster recurrence — EXACT R10 version (best measured: 1183 us).
// Chunked full barriers, wait-free producer stores (empty barriers proven
// redundant via the full-barrier causal chain), elected re-arm after wait,
// shfl pre-reduce, double-buffered red, one block barrier per step.
// ---------------------------------------------------------------------------
#define CLUSTER       8
#define NCTA          128
#define BATCH_PER_CL  4
#define COLS_PER_CTA  64

#define HBUF_ELEMS  (2 * BATCH_PER_CL * HH)              // 4096 floats (16 KB)
#define RED16_ELEMS (16 * BATCH_PER_CL * COLS_PER_CTA)   // 4096 floats (16 KB)
#define MBAR_OFF    ((HBUF_ELEMS + 2 * RED16_ELEMS) * 4) // 49152 bytes
#define MB_FULL(p, r) (MBAR_OFF + ((p) * 8 + (r)) * 8)
#define RNN_SMEM_BYTES (MBAR_OFF + 128)

#define CHUNK_TX_BYTES 1024   // 128 producer threads x 8 B land per peer chunk

__global__ __launch_bounds__(512, 1) __cluster_dims__(CLUSTER, 1, 1)
void rnn_cluster_kernel(const float* __restrict__ h0,
                        const float* __restrict__ Wh,
                        float* __restrict__ out)
{
    extern __shared__ float smem[];
    float* hbuf = smem;                       // [2][4][HH]
    float* red  = smem + HBUF_ELEMS;          // [2][16][4][64]

    const int tid = threadIdx.x;
    uint32_t rank;
    asm("mov.u32 %0, %%cluster_ctarank;" : "=r"(rank));
    const int cid = blockIdx.x >> 3;
    const int b0  = cid * BATCH_PER_CL;

    const int kq    = tid >> 4;          // 0..31
    const int cq    = tid & 15;          // 0..15
    const int kbase = kq * 16;
    const int kq2   = tid >> 5;          // warp id 0..15
    const int chunk = tid >> 6;          // 0..7: source rank my warp consumes
    const int jg0   = (int)rank * COLS_PER_CTA + cq * 4;

    // ---- Wh slice -> registers (once) ----
    unsigned long long w01[16], w23[16];
#pragma unroll
    for (int kk = 0; kk < 16; ++kk) {
        ulonglong2 v = *reinterpret_cast<const ulonglong2*>(
            Wh + (size_t)(kbase + kk) * HH + jg0);
        w01[kk] = v.x;
        w23[kk] = v.y;
    }

    uint32_t smem_u32;
    asm("{ .reg .u64 t; cvta.to.shared.u64 t, %1; cvt.u32.u64 %0, t; }"
        : "=r"(smem_u32) : "l"(smem));

    // ---- init: mbarriers + h0 into buffer 0 ----
    if (tid == 0) {
#pragma unroll
        for (int r = 0; r < CLUSTER; ++r) {
            MBAR_INIT(smem_u32 + MB_FULL(0, r), 1);
            MBAR_INIT(smem_u32 + MB_FULL(1, r), 1);
            MBAR_EXPECT_TX(smem_u32 + MB_FULL(0, r), CHUNK_TX_BYTES);
            MBAR_EXPECT_TX(smem_u32 + MB_FULL(1, r), CHUNK_TX_BYTES);
        }
    }
    for (int idx = tid; idx < BATCH_PER_CL * HH; idx += 512)
        hbuf[idx] = h0[(size_t)b0 * HH + idx];
    __syncthreads();
    asm volatile("barrier.cluster.arrive.aligned;\n\t"
                 "barrier.cluster.wait.aligned;" ::: "memory");

    // peer smem base addresses (mapa once)
    uint32_t rbase[CLUSTER];
#pragma unroll
    for (int p = 0; p < CLUSTER; ++p)
        asm("mapa.shared::cluster.u32 %0, %1, %2;"
            : "=r"(rbase[p]) : "r"(smem_u32), "r"(p));

    // output-stage mapping (threads < 256)
    const int fb = (tid >> 6) & 3;
    const int fc = tid & 63;
    const int jg = (int)rank * COLS_PER_CTA + fc;
    float* outp = out + ((size_t)(b0 + fb) * TT) * HH + jg;
    const bool is_red   = (tid < 256);
    const bool is_store = (tid < 256) && ((tid & 1) == 0);
    const bool is_arm   = ((tid & 63) == 0);   // one re-armer per chunk
    const bool is_lo    = ((tid & 16) == 0);   // lane < 16 within warp

    int pf[2] = {0, 0};   // per-warp parity for full[buf][chunk]

#pragma unroll 2
    for (int t = 0; t < TT; ++t) {
        const int p = t & 1;
        const int q = p ^ 1;

        // prefetch xwx for this step (independent of h)
        float xw = 0.0f;
        if (is_red) xw = outp[(size_t)t * HH];

        // wait only for MY chunk of h_t; elected thread re-arms immediately.
        if (t > 0) {
            mbar_wait_parity(smem_u32 + MB_FULL(p, chunk), (uint32_t)pf[p]);
            pf[p] ^= 1;
            if (is_arm)
                MBAR_EXPECT_TX(smem_u32 + MB_FULL(p, chunk), CHUNK_TX_BYTES);
        }

        const float* hc = hbuf + p * (BATCH_PER_CL * HH);
        unsigned long long a01[4] = {0ULL, 0ULL, 0ULL, 0ULL};
        unsigned long long a23[4] = {0ULL, 0ULL, 0ULL, 0ULL};

#pragma unroll
        for (int kk4 = 0; kk4 < 4; ++kk4) {
            const int k = kbase + kk4 * 4;
#pragma unroll
            for (int b = 0; b < 4; ++b) {
                float4 hv = *reinterpret_cast<const float4*>(&hc[b * HH + k]);
                unsigned long long hh;
                hh = pack_dup(hv.x);
                ffma2(a01[b], hh, w01[kk4 * 4 + 0]);
                ffma2(a23[b], hh, w23[kk4 * 4 + 0]);
                hh = pack_dup(hv.y);
                ffma2(a01[b], hh, w01[kk4 * 4 + 1]);
                ffma2(a23[b], hh, w23[kk4 * 4 + 1]);
                hh = pack_dup(hv.z);
                ffma2(a01[b], hh, w01[kk4 * 4 + 2]);
                ffma2(a23[b], hh, w23[kk4 * 4 + 2]);
                hh = pack_dup(hv.w);
                ffma2(a01[b], hh, w01[kk4 * 4 + 3]);
                ffma2(a23[b], hh, w23[kk4 * 4 + 3]);
            }
        }

        // warp pre-reduce: lane L += lane L+16 (kq pair, same cols)
#pragma unroll
        for (int b = 0; b < 4; ++b) {
            a01[b] = add2(a01[b], shfl_down16_b64(a01[b]));
            a23[b] = add2(a23[b], shfl_down16_b64(a23[b]));
        }

        // pre-reduced partials -> red[p][kq2][b][4cq..4cq+3] (lanes < 16)
        float* rp = red + p * RED16_ELEMS;
        if (is_lo) {
#pragma unroll
            for (int b = 0; b < 4; ++b) {
                ulonglong2 v;
                v.x = a01[b];
                v.y = a23[b];
                *reinterpret_cast<ulonglong2*>(
                    &rp[(kq2 * BATCH_PER_CL + b) * COLS_PER_CTA + cq * 4]) = v;
            }
        }
        __syncthreads();   // the ONLY block barrier per step

        if (is_red) {
            // 16-way reduce, 4 parallel chains
            float s0 = xw, s1 = 0.f, s2 = 0.f, s3 = 0.f;
#pragma unroll
            for (int qd = 0; qd < 4; ++qd) {
                s0 += rp[((4 * qd + 0) * BATCH_PER_CL + fb) * COLS_PER_CTA + fc];
                s1 += rp[((4 * qd + 1) * BATCH_PER_CL + fb) * COLS_PER_CTA + fc];
                s2 += rp[((4 * qd + 2) * BATCH_PER_CL + fb) * COLS_PER_CTA + fc];
                s3 += rp[((4 * qd + 3) * BATCH_PER_CL + fb) * COLS_PER_CTA + fc];
            }
            float s = (s0 + s1) + (s2 + s3);
            float r;
            asm("tanh.approx.f32 %0, %1;" : "=f"(r) : "f"(s));
            outp[(size_t)t * HH] = r;

            if (t + 1 < TT) {
                // WAIT-FREE store (causal chain; see header comment).
                float rn = __shfl_down_sync(0xFFFFFFFFu, r, 1);
                if (is_store) {
                    unsigned long long v = pack2(r, rn);
                    const uint32_t off =
                        (uint32_t)((q * BATCH_PER_CL + fb) * HH + jg) * 4u;
                    const uint32_t mboff = (uint32_t)MB_FULL(q, (int)rank);
#pragma unroll
                    for (int pp = 0; pp < CLUSTER; ++pp)
                        st_async_b64(rbase[pp] + off, v, rbase[pp] + mboff);
                }
            }
        }
        // no trailing barrier: red double-buffered; cross-step ordering
        // guaranteed by bar(t) between reduce-read(t-1) and STS(t+1).
    }

    // drain before exit
    asm volatile("barrier.cluster.arrive.aligned;\n\t"
                 "barrier.cluster.wait.aligned;" ::: "memory");
}

// ---------------------------------------------------------------------------
// Launch
// ---------------------------------------------------------------------------
extern "C" void kernel_launch(void* const* d_in, const int* in_sizes, int n_in,
                              void* d_out, int out_size) {
    const float* x  = (const float*)d_in[0];
    const float* h0 = (const float*)d_in[1];
    const float* Wx = (const float*)d_in[2];
    const float* Wh = (const float*)d_in[3];
    const float* b  = (const float*)d_in[4];
    float* out = (float*)d_out;

    (void)in_sizes; (void)n_in; (void)out_size;

    dim3 gridA(HH / BN, MM / BM);
    gemm_xwx_kernel<<<gridA, 256>>>(x, Wx, b, out);

    cudaFuncSetAttribute(rnn_cluster_kernel,
                         cudaFuncAttributeMaxDynamicSharedMemorySize,
                         RNN_SMEM_BYTES);
    rnn_cluster_kernel<<<NCTA, 512, RNN_SMEM_BYTES>>>(h0, Wh, out);
}